// round 5
// baseline (speedup 1.0000x reference)
#include <cuda_runtime.h>
#include <cuda_bf16.h>
#include <math.h>

// ---------------------------------------------------------------------------
// Problem constants
// ---------------------------------------------------------------------------
#define L_SEQ   2516          // 16 + 25*100
#define C_DIM   128
#define HEADS_N 8
#define DH      16
#define MLP_DIM 512
#define N_IMG   100           // 25 support + 75 query
#define HW      100           // 10x10
#define T_CH    32
#define KSPAN   256           // keys per split (multiple of 64)
#define KSPLIT  10            // ceil(2516/256)

typedef unsigned long long ull;

// ---- packed fp32x2 helpers (Blackwell FFMA2; bit-identical per-lane fp32) --
__device__ __forceinline__ ull mul2(ull a, ull b) {
    ull r; asm("mul.rn.f32x2 %0,%1,%2;" : "=l"(r) : "l"(a), "l"(b)); return r;
}
__device__ __forceinline__ void fma2(ull &d, ull a, ull b) {
    asm("fma.rn.f32x2 %0,%1,%2,%0;" : "+l"(d) : "l"(a), "l"(b));
}
__device__ __forceinline__ ull add2(ull a, ull b) {
    ull r; asm("add.rn.f32x2 %0,%1,%2;" : "=l"(r) : "l"(a), "l"(b)); return r;
}
__device__ __forceinline__ ull pack2(float x, float y) {
    ull r; asm("mov.b64 %0,{%1,%2};" : "=l"(r) : "f"(x), "f"(y)); return r;
}
__device__ __forceinline__ float2 unpack2(ull a) {
    float x, y; asm("mov.b64 {%0,%1},%2;" : "=f"(x), "=f"(y) : "l"(a));
    return make_float2(x, y);
}

// ---------------------------------------------------------------------------
// Scratch (device globals; no allocation allowed)
// ---------------------------------------------------------------------------
__device__ float g_X   [L_SEQ * C_DIM];
__device__ float g_QKV [L_SEQ * 3 * C_DIM];
__device__ float g_O   [L_SEQ * C_DIM];
__device__ float g_G   [L_SEQ * MLP_DIM];
__device__ float g_PART[KSPLIT * HEADS_N * L_SEQ * DH];
__device__ float g_ML  [KSPLIT * HEADS_N * L_SEQ * 2];
__device__ float g_FUSED[N_IMG * C_DIM * HW];
__device__ float g_LNT  [N_IMG * C_DIM * HW];
__device__ float g_T1   [N_IMG * T_CH * HW];
__device__ float g_T2   [N_IMG * T_CH * HW];

// ---------------------------------------------------------------------------
// build X = concat(task_descriptor, support permuted)
// ---------------------------------------------------------------------------
__global__ void build_x_k(const float* __restrict__ task,
                          const float* __restrict__ support,
                          float* __restrict__ X)
{
    int i = blockIdx.x * blockDim.x + threadIdx.x;
    if (i >= L_SEQ * C_DIM) return;
    int r = i >> 7;
    int c = i & 127;
    if (r < 16) {
        X[i] = task[r * C_DIM + c];
    } else {
        int rr = r - 16;
        int b = rr / HW, p = rr % HW;
        X[i] = support[b * C_DIM * HW + c * HW + p];
    }
}

// ---------------------------------------------------------------------------
// Fused (optional rowLN) + GEMM for K = 128.
// C[M,N] = LN(A)[M,128] @ B[128,N] + epi.  epi: 0=+bias, 1=+bias+res, 2=gelu.
// BM=64, BN=64, 256 threads, whole K staged transposed in smem.
// ---------------------------------------------------------------------------
__global__ void __launch_bounds__(256) ln_gemm_k(
    const float* __restrict__ A, const float* __restrict__ B,
    const float* __restrict__ bias, const float* __restrict__ res,
    float* __restrict__ C, int M, int N,
    const float* __restrict__ lg, const float* __restrict__ lb,
    int do_ln, int epi)
{
    __shared__ __align__(16) float Ast[128][68];   // [k][row]
    __shared__ __align__(16) float Bs[32][64];
    __shared__ float sg[128], sb[128];
    int bm = blockIdx.y * 64, bn = blockIdx.x * 64;
    int tid = threadIdx.x;
    if (do_ln && tid < 128) { sg[tid] = lg[tid]; sb[tid] = lb[tid]; }

    // --- load 64x128 A tile: 4 threads per row ---
    int row = tid >> 2, part = tid & 3;
    int grow = bm + row;
    float4 v[8];
#pragma unroll
    for (int i = 0; i < 8; i++) {
        int c = i * 16 + part * 4;
        v[i] = (grow < M) ? *(const float4*)&A[(size_t)grow * 128 + c]
                          : make_float4(0.f, 0.f, 0.f, 0.f);
    }
    __syncthreads();   // sg/sb visible

    if (do_ln) {
        float s = 0.f;
#pragma unroll
        for (int i = 0; i < 8; i++) s += (v[i].x + v[i].y) + (v[i].z + v[i].w);
        s += __shfl_xor_sync(0xFFFFFFFFu, s, 1);
        s += __shfl_xor_sync(0xFFFFFFFFu, s, 2);
        float mean = s * (1.0f / 128.0f);
        float vv = 0.f;
#pragma unroll
        for (int i = 0; i < 8; i++) {
            float dx = v[i].x - mean, dy = v[i].y - mean;
            float dz = v[i].z - mean, dw = v[i].w - mean;
            vv += (dx * dx + dy * dy) + (dz * dz + dw * dw);
        }
        vv += __shfl_xor_sync(0xFFFFFFFFu, vv, 1);
        vv += __shfl_xor_sync(0xFFFFFFFFu, vv, 2);
        float rs = rsqrtf(vv * (1.0f / 128.0f) + 1e-5f);
#pragma unroll
        for (int i = 0; i < 8; i++) {
            int c = i * 16 + part * 4;
            v[i].x = (v[i].x - mean) * rs * sg[c + 0] + sb[c + 0];
            v[i].y = (v[i].y - mean) * rs * sg[c + 1] + sb[c + 1];
            v[i].z = (v[i].z - mean) * rs * sg[c + 2] + sb[c + 2];
            v[i].w = (v[i].w - mean) * rs * sg[c + 3] + sb[c + 3];
        }
    }
#pragma unroll
    for (int i = 0; i < 8; i++) {
        int c = i * 16 + part * 4;
        Ast[c + 0][row] = v[i].x;
        Ast[c + 1][row] = v[i].y;
        Ast[c + 2][row] = v[i].z;
        Ast[c + 3][row] = v[i].w;
    }
    __syncthreads();

    int tx = tid & 15, ty = tid >> 4;
    ull acc01[4] = {0, 0, 0, 0}, acc23[4] = {0, 0, 0, 0};

    for (int kk = 0; kk < 128; kk += 32) {
        if (kk) __syncthreads();
        // stage B chunk 32x64 (2 float4 / thread)
#pragma unroll
        for (int u = 0; u < 2; u++) {
            int idx = tid * 2 + u;
            int brow = idx >> 4, bcol = (idx & 15) * 4;
            *(float4*)&Bs[brow][bcol] =
                *(const float4*)&B[(size_t)(kk + brow) * N + bn + bcol];
        }
        __syncthreads();
#pragma unroll
        for (int k = 0; k < 32; k++) {
            float4 a4 = *(const float4*)&Ast[kk + k][ty * 4];
            ulonglong2 bp = *(const ulonglong2*)&Bs[k][tx * 4];
            ull aa;
            aa = pack2(a4.x, a4.x); fma2(acc01[0], aa, bp.x); fma2(acc23[0], aa, bp.y);
            aa = pack2(a4.y, a4.y); fma2(acc01[1], aa, bp.x); fma2(acc23[1], aa, bp.y);
            aa = pack2(a4.z, a4.z); fma2(acc01[2], aa, bp.x); fma2(acc23[2], aa, bp.y);
            aa = pack2(a4.w, a4.w); fma2(acc01[3], aa, bp.x); fma2(acc23[3], aa, bp.y);
        }
    }

#pragma unroll
    for (int i = 0; i < 4; i++) {
        int r = bm + ty * 4 + i;
        if (r >= M) continue;
        float2 c01 = unpack2(acc01[i]);
        float2 c23 = unpack2(acc23[i]);
        float vals[4] = {c01.x, c01.y, c23.x, c23.y};
#pragma unroll
        for (int j = 0; j < 4; j++) {
            int cidx = bn + tx * 4 + j;
            float o = vals[j] + bias[cidx];
            if (epi == 1) o += res[(size_t)r * N + cidx];
            else if (epi == 2) o = 0.5f * o * (1.0f + erff(o * 0.70710678118654752f));
            C[(size_t)r * N + cidx] = o;
        }
    }
}

// ---------------------------------------------------------------------------
// Streaming-K GEMM (for K=512), f32x2 inner. BM=BN=64, BK=16, epi=+bias+res.
// ---------------------------------------------------------------------------
__global__ void __launch_bounds__(256) gemm_sk_k(
    const float* __restrict__ A, const float* __restrict__ B,
    const float* __restrict__ bias, const float* __restrict__ res,
    float* __restrict__ C, int M, int N, int K)
{
    __shared__ __align__(16) float As[16][68];
    __shared__ __align__(16) float Bs[16][64];
    int bm = blockIdx.y * 64, bn = blockIdx.x * 64;
    int tid = threadIdx.x;
    int tx = tid & 15, ty = tid >> 4;
    ull acc01[4] = {0, 0, 0, 0}, acc23[4] = {0, 0, 0, 0};

    int ar = tid >> 2, ac = (tid & 3) * 4;
    int brow = tid >> 4, bcol = (tid & 15) * 4;

    for (int k0 = 0; k0 < K; k0 += 16) {
        float4 av = make_float4(0.f, 0.f, 0.f, 0.f);
        if (bm + ar < M)
            av = *(const float4*)&A[(size_t)(bm + ar) * K + k0 + ac];
        As[ac + 0][ar] = av.x;
        As[ac + 1][ar] = av.y;
        As[ac + 2][ar] = av.z;
        As[ac + 3][ar] = av.w;
        *(float4*)&Bs[brow][bcol] = *(const float4*)&B[(size_t)(k0 + brow) * N + bn + bcol];
        __syncthreads();
#pragma unroll
        for (int k = 0; k < 16; k++) {
            float4 a4 = *(const float4*)&As[k][ty * 4];
            ulonglong2 bp = *(const ulonglong2*)&Bs[k][tx * 4];
            ull aa;
            aa = pack2(a4.x, a4.x); fma2(acc01[0], aa, bp.x); fma2(acc23[0], aa, bp.y);
            aa = pack2(a4.y, a4.y); fma2(acc01[1], aa, bp.x); fma2(acc23[1], aa, bp.y);
            aa = pack2(a4.z, a4.z); fma2(acc01[2], aa, bp.x); fma2(acc23[2], aa, bp.y);
            aa = pack2(a4.w, a4.w); fma2(acc01[3], aa, bp.x); fma2(acc23[3], aa, bp.y);
        }
        __syncthreads();
    }
#pragma unroll
    for (int i = 0; i < 4; i++) {
        int r = bm + ty * 4 + i;
        if (r >= M) continue;
        float2 c01 = unpack2(acc01[i]);
        float2 c23 = unpack2(acc23[i]);
        float vals[4] = {c01.x, c01.y, c23.x, c23.y};
#pragma unroll
        for (int j = 0; j < 4; j++) {
            int cidx = bn + tx * 4 + j;
            float o = vals[j] + bias[cidx] + res[(size_t)r * N + cidx];
            C[(size_t)r * N + cidx] = o;
        }
    }
}

// ---------------------------------------------------------------------------
// Flash attention partials: 2 queries/thread x 2 keys/iter, f32x2 math.
// grid (10, heads=8, splits=10), block 128.
// ---------------------------------------------------------------------------
__global__ void __launch_bounds__(128)
attn_partial_k(const float* __restrict__ QKV,
               float* __restrict__ PART, float* __restrict__ ML)
{
    int h  = blockIdx.y;
    int sp = blockIdx.z;
    int tid = threadIdx.x;
    int q0 = blockIdx.x * 256 + tid;
    int q1 = q0 + 128;
    int k0 = sp * KSPAN;
    int k1 = min(L_SEQ, k0 + KSPAN);

    __shared__ __align__(16) float4 Ks[64][4];
    __shared__ __align__(16) float4 Vs[64][4];

    bool act0 = q0 < L_SEQ, act1 = q1 < L_SEQ;
    ull qa[8], qb[8];
#pragma unroll
    for (int u = 0; u < 4; u++) {
        ulonglong2 t = act0 ? *(const ulonglong2*)&QKV[(size_t)q0 * 384 + h * 16 + 4 * u]
                            : make_ulonglong2(0ull, 0ull);
        qa[2 * u] = t.x; qa[2 * u + 1] = t.y;
        ulonglong2 s = act1 ? *(const ulonglong2*)&QKV[(size_t)q1 * 384 + h * 16 + 4 * u]
                            : make_ulonglong2(0ull, 0ull);
        qb[2 * u] = s.x; qb[2 * u + 1] = s.y;
    }
    float m0 = -INFINITY, l0 = 0.f, m1 = -INFINITY, l1 = 0.f;
    ull A0[8] = {0,0,0,0,0,0,0,0}, A1[8] = {0,0,0,0,0,0,0,0};

    for (int kc = k0; kc < k1; kc += 64) {
        int n = min(64, k1 - kc);
        for (int idx = tid; idx < n * 4; idx += 128) {
            int row = idx >> 2, d4 = idx & 3;
            Ks[row][d4] = *(const float4*)&QKV[(size_t)(kc + row) * 384 + 128 + h * 16 + 4 * d4];
            Vs[row][d4] = *(const float4*)&QKV[(size_t)(kc + row) * 384 + 256 + h * 16 + 4 * d4];
        }
        __syncthreads();
        for (int j = 0; j + 2 <= n; j += 2) {
            ull ka[8], kb[8];
#pragma unroll
            for (int u = 0; u < 4; u++) {
                ulonglong2 t = *(const ulonglong2*)&Ks[j][u];
                ka[2 * u] = t.x; ka[2 * u + 1] = t.y;
                ulonglong2 s = *(const ulonglong2*)&Ks[j + 1][u];
                kb[2 * u] = s.x; kb[2 * u + 1] = s.y;
            }
            // scores
            ull c0, c1;
            c0 = mul2(qa[0], ka[0]); c1 = mul2(qa[1], ka[1]);
            fma2(c0, qa[2], ka[2]);  fma2(c1, qa[3], ka[3]);
            fma2(c0, qa[4], ka[4]);  fma2(c1, qa[5], ka[5]);
            fma2(c0, qa[6], ka[6]);  fma2(c1, qa[7], ka[7]);
            float2 f00 = unpack2(add2(c0, c1));
            float s00 = (f00.x + f00.y) * 0.25f;

            c0 = mul2(qa[0], kb[0]); c1 = mul2(qa[1], kb[1]);
            fma2(c0, qa[2], kb[2]);  fma2(c1, qa[3], kb[3]);
            fma2(c0, qa[4], kb[4]);  fma2(c1, qa[5], kb[5]);
            fma2(c0, qa[6], kb[6]);  fma2(c1, qa[7], kb[7]);
            float2 f01 = unpack2(add2(c0, c1));
            float s01 = (f01.x + f01.y) * 0.25f;

            c0 = mul2(qb[0], ka[0]); c1 = mul2(qb[1], ka[1]);
            fma2(c0, qb[2], ka[2]);  fma2(c1, qb[3], ka[3]);
            fma2(c0, qb[4], ka[4]);  fma2(c1, qb[5], ka[5]);
            fma2(c0, qb[6], ka[6]);  fma2(c1, qb[7], ka[7]);
            float2 f10 = unpack2(add2(c0, c1));
            float s10 = (f10.x + f10.y) * 0.25f;

            c0 = mul2(qb[0], kb[0]); c1 = mul2(qb[1], kb[1]);
            fma2(c0, qb[2], kb[2]);  fma2(c1, qb[3], kb[3]);
            fma2(c0, qb[4], kb[4]);  fma2(c1, qb[5], kb[5]);
            fma2(c0, qb[6], kb[6]);  fma2(c1, qb[7], kb[7]);
            float2 f11 = unpack2(add2(c0, c1));
            float s11 = (f11.x + f11.y) * 0.25f;

            float mp0 = fmaxf(s00, s01);
            if (mp0 > m0) {
                float corr = __expf(m0 - mp0);
                l0 *= corr;
                ull cc = pack2(corr, corr);
#pragma unroll
                for (int u = 0; u < 8; u++) A0[u] = mul2(A0[u], cc);
                m0 = mp0;
            }
            float p00 = __expf(s00 - m0), p01 = __expf(s01 - m0);
            l0 += p00 + p01;

            float mp1 = fmaxf(s10, s11);
            if (mp1 > m1) {
                float corr = __expf(m1 - mp1);
                l1 *= corr;
                ull cc = pack2(corr, corr);
#pragma unroll
                for (int u = 0; u < 8; u++) A1[u] = mul2(A1[u], cc);
                m1 = mp1;
            }
            float p10 = __expf(s10 - m1), p11 = __expf(s11 - m1);
            l1 += p10 + p11;

            ull pp00 = pack2(p00, p00), pp01 = pack2(p01, p01);
            ull pp10 = pack2(p10, p10), pp11 = pack2(p11, p11);
#pragma unroll
            for (int u = 0; u < 4; u++) {
                ulonglong2 va = *(const ulonglong2*)&Vs[j][u];
                ulonglong2 vb = *(const ulonglong2*)&Vs[j + 1][u];
                fma2(A0[2 * u],     pp00, va.x); fma2(A0[2 * u],     pp01, vb.x);
                fma2(A0[2 * u + 1], pp00, va.y); fma2(A0[2 * u + 1], pp01, vb.y);
                fma2(A1[2 * u],     pp10, va.x); fma2(A1[2 * u],     pp11, vb.x);
                fma2(A1[2 * u + 1], pp10, va.y); fma2(A1[2 * u + 1], pp11, vb.y);
            }
        }
        __syncthreads();
    }
    if (act0) {
        size_t idx = ((size_t)(sp * HEADS_N + h) * L_SEQ + q0);
        ulonglong2* pb = (ulonglong2*)&PART[idx * 16];
#pragma unroll
        for (int u = 0; u < 4; u++) pb[u] = make_ulonglong2(A0[2 * u], A0[2 * u + 1]);
        ML[idx * 2 + 0] = m0;
        ML[idx * 2 + 1] = l0;
    }
    if (act1) {
        size_t idx = ((size_t)(sp * HEADS_N + h) * L_SEQ + q1);
        ulonglong2* pb = (ulonglong2*)&PART[idx * 16];
#pragma unroll
        for (int u = 0; u < 4; u++) pb[u] = make_ulonglong2(A1[2 * u], A1[2 * u + 1]);
        ML[idx * 2 + 0] = m1;
        ML[idx * 2 + 1] = l1;
    }
}

__global__ void attn_merge_k(const float* __restrict__ PART, const float* __restrict__ ML,
                             float* __restrict__ O)
{
    int t = blockIdx.x * blockDim.x + threadIdx.x;
    if (t >= HEADS_N * L_SEQ) return;
    int h = t / L_SEQ, q = t % L_SEQ;
    float mm[KSPLIT], ll[KSPLIT];
    float M = -INFINITY;
#pragma unroll
    for (int sp = 0; sp < KSPLIT; sp++) {
        size_t idx = ((size_t)(sp * HEADS_N + h) * L_SEQ + q);
        mm[sp] = ML[idx * 2 + 0];
        ll[sp] = ML[idx * 2 + 1];
        M = fmaxf(M, mm[sp]);
    }
    float wsum = 0.0f, w[KSPLIT];
#pragma unroll
    for (int sp = 0; sp < KSPLIT; sp++) {
        w[sp] = __expf(mm[sp] - M);
        wsum += ll[sp] * w[sp];
    }
    float inv = 1.0f / wsum;
    float o[DH];
#pragma unroll
    for (int d = 0; d < DH; d++) o[d] = 0.0f;
#pragma unroll
    for (int sp = 0; sp < KSPLIT; sp++) {
        size_t idx = ((size_t)(sp * HEADS_N + h) * L_SEQ + q);
        const float4* pb = (const float4*)&PART[idx * 16];
#pragma unroll
        for (int u = 0; u < 4; u++) {
            float4 v = pb[u];
            o[4 * u + 0] += v.x * w[sp];
            o[4 * u + 1] += v.y * w[sp];
            o[4 * u + 2] += v.z * w[sp];
            o[4 * u + 3] += v.w * w[sp];
        }
    }
#pragma unroll
    for (int d = 0; d < DH; d++)
        O[(size_t)q * C_DIM + h * DH + d] = o[d] * inv;
}

// ---------------------------------------------------------------------------
// Fused region + map_fuse + channel LayerNorm. One block/image, 128 threads.
// ---------------------------------------------------------------------------
__global__ void region_lnchan_k(const float* __restrict__ support,
                                const float* __restrict__ query,
                                const float* __restrict__ X,
                                const float* __restrict__ rg,
                                const float* __restrict__ rb,
                                float* __restrict__ F,
                                float* __restrict__ LNT)
{
    int img = blockIdx.x;
    __shared__ float key[16 * C_DIM];
    for (int i = threadIdx.x; i < 16 * C_DIM; i += 128) key[i] = X[i];
    __syncthreads();
    const float* feat = (img < 25) ? support + (size_t)img * C_DIM * HW
                                   : query + (size_t)(img - 25) * C_DIM * HW;
    float* fb  = F   + (size_t)img * C_DIM * HW;
    float* lb_ = LNT + (size_t)img * C_DIM * HW;
    int p = threadIdx.x;
    if (p >= HW) return;

    float dot[16];
#pragma unroll
    for (int m = 0; m < 16; m++) dot[m] = 0.0f;
    float fsum = 0.0f;
    for (int c = 0; c < C_DIM; c++) {
        float f = feat[c * HW + p];
        fsum += f;
#pragma unroll
        for (int m = 0; m < 16; m++) dot[m] += key[m * C_DIM + c] * f;
    }
    float s = 0.0f;
#pragma unroll
    for (int m = 0; m < 16; m++)
        s += 1.0f / (1.0f + __expf(-dot[m] * (1.0f / 128.0f)));
    s = s * (1.0f / 16.0f) + 1.0f;

    float mean = s * fsum * (1.0f / 128.0f);
    float var = 0.0f;
    for (int c = 0; c < C_DIM; c++) {
        float d = feat[c * HW + p] * s - mean;
        var += d * d;
    }
    float rs = rsqrtf(var * (1.0f / 128.0f) + 1e-6f);
    for (int c = 0; c < C_DIM; c++) {
        float fu = feat[c * HW + p] * s;
        fb[c * HW + p] = fu;
        lb_[c * HW + p] = (fu - mean) * rs * rg[c] + rb[c];
    }
}

// ---------------------------------------------------------------------------
// 3x3 conv, pad 1, 10x10, Cout=32. grid (image, 4): 8 oc/block, 256 threads.
// ---------------------------------------------------------------------------
__global__ void conv3x3_k(const float* __restrict__ in, const float* __restrict__ w,
                          float* __restrict__ out, int Cin, int do_relu)
{
    extern __shared__ float s_in[];  // Cin*144
    int img = blockIdx.x;
    int tid = threadIdx.x;
    const float* inb = in + (size_t)img * Cin * HW;
    for (int idx = tid; idx < Cin * 144; idx += 256) {
        int c = idx / 144, pos = idx % 144;
        int y = pos / 12 - 1, x = pos % 12 - 1;
        float v = 0.0f;
        if (y >= 0 && y < 10 && x >= 0 && x < 10) v = inb[c * HW + y * 10 + x];
        s_in[idx] = v;
    }
    __syncthreads();

    int oc = blockIdx.y * 8 + (tid >> 5);
    int lane = tid & 31;
    float acc[4];
    int base[4];
#pragma unroll
    for (int t = 0; t < 4; t++) {
        acc[t] = 0.0f;
        int p = lane + 32 * t;
        if (p > 99) p = 99;
        int y = p / 10, x = p % 10;
        base[t] = y * 12 + x;
    }
    const float* wb = w + (size_t)oc * Cin * 9;
    for (int c = 0; c < Cin; c++) {
        const float* sc = s_in + c * 144;
#pragma unroll
        for (int kk = 0; kk < 9; kk++) {
            float wv = wb[c * 9 + kk];
            int off = (kk / 3) * 12 + (kk % 3);
#pragma unroll
            for (int t = 0; t < 4; t++)
                acc[t] += sc[base[t] + off] * wv;
        }
    }
    float* ob = out + (size_t)img * T_CH * HW + oc * HW;
#pragma unroll
    for (int t = 0; t < 4; t++) {
        int p = lane + 32 * t;
        if (p < HW) {
            float v = acc[t];
            if (do_relu) v = fmaxf(v, 0.0f);
            ob[p] = v;
        }
    }
}

// ---------------------------------------------------------------------------
// Final: out[b][c][t] = (1/100) * sum_p sigmoid(T4[b][t][p]) * F[b][c][p]
// ---------------------------------------------------------------------------
__global__ void rfm_out_k(const float* __restrict__ T4, const float* __restrict__ F,
                          float* __restrict__ out)
{
    int img = blockIdx.x;
    __shared__ float sig[HW * T_CH];  // [p][t]
    int tid = threadIdx.x;
    for (int idx = tid; idx < T_CH * HW; idx += 256) {
        int t = idx / HW, p = idx % HW;
        float v = T4[(size_t)img * T_CH * HW + idx];
        sig[p * T_CH + t] = 1.0f / (1.0f + __expf(-v));
    }
    __syncthreads();
    float* ob = out + (size_t)img * 4096;
    const float* fb = F + (size_t)img * C_DIM * HW;
    for (int o = tid; o < C_DIM * T_CH; o += 256) {
        int c = o >> 5, t = o & 31;
        float s = 0.0f;
        for (int p = 0; p < HW; p++)
            s += fb[c * HW + p] * sig[p * T_CH + t];
        ob[c * T_CH + t] = s * (1.0f / 100.0f);
    }
}

// ---------------------------------------------------------------------------
// Host launcher
// ---------------------------------------------------------------------------
extern "C" void kernel_launch(void* const* d_in, const int* in_sizes, int n_in,
                              void* d_out, int out_size)
{
    const float* support = (const float*)d_in[0];
    const float* query   = (const float*)d_in[1];
    const float* task    = (const float*)d_in[2];
    const float* ln1_g   = (const float*)d_in[3];
    const float* ln1_b   = (const float*)d_in[4];
    const float* qkv_w   = (const float*)d_in[5];
    const float* qkv_b   = (const float*)d_in[6];
    const float* out_w   = (const float*)d_in[7];
    const float* out_b   = (const float*)d_in[8];
    const float* ln2_g   = (const float*)d_in[9];
    const float* ln2_b   = (const float*)d_in[10];
    const float* mlp_w1  = (const float*)d_in[11];
    const float* mlp_b1  = (const float*)d_in[12];
    const float* mlp_w2  = (const float*)d_in[13];
    const float* mlp_b2  = (const float*)d_in[14];
    const float* rln_g   = (const float*)d_in[15];
    const float* rln_b   = (const float*)d_in[16];
    const float* conv1   = (const float*)d_in[17];
    const float* conv2   = (const float*)d_in[18];
    const float* conv3   = (const float*)d_in[19];
    const float* conv4   = (const float*)d_in[20];

    float *X, *QKV, *O, *G, *PART, *ML, *FUSED, *LNT, *T1, *T2;
    cudaGetSymbolAddress((void**)&X, g_X);
    cudaGetSymbolAddress((void**)&QKV, g_QKV);
    cudaGetSymbolAddress((void**)&O, g_O);
    cudaGetSymbolAddress((void**)&G, g_G);
    cudaGetSymbolAddress((void**)&PART, g_PART);
    cudaGetSymbolAddress((void**)&ML, g_ML);
    cudaGetSymbolAddress((void**)&FUSED, g_FUSED);
    cudaGetSymbolAddress((void**)&LNT, g_LNT);
    cudaGetSymbolAddress((void**)&T1, g_T1);
    cudaGetSymbolAddress((void**)&T2, g_T2);

    cudaFuncSetAttribute(conv3x3_k, cudaFuncAttributeMaxDynamicSharedMemorySize,
                         C_DIM * 144 * sizeof(float));

    build_x_k<<<(L_SEQ * C_DIM + 255) / 256, 256>>>(task, support, X);

    for (int i = 0; i < 2; i++) {
        // LN1 + qkv
        ln_gemm_k<<<dim3(6, 40), 256>>>(X, qkv_w + (size_t)i * C_DIM * 384,
                                        qkv_b + i * 384, nullptr, QKV,
                                        L_SEQ, 384,
                                        ln1_g + i * C_DIM, ln1_b + i * C_DIM, 1, 0);
        attn_partial_k<<<dim3(10, HEADS_N, KSPLIT), 128>>>(QKV, PART, ML);
        attn_merge_k<<<(HEADS_N * L_SEQ + 127) / 128, 128>>>(PART, ML, O);
        // proj + residual (no LN)
        ln_gemm_k<<<dim3(2, 40), 256>>>(O, out_w + (size_t)i * C_DIM * C_DIM,
                                        out_b + i * C_DIM, X, X,
                                        L_SEQ, 128, nullptr, nullptr, 0, 1);
        // LN2 + mlp1 + gelu
        ln_gemm_k<<<dim3(8, 40), 256>>>(X, mlp_w1 + (size_t)i * C_DIM * MLP_DIM,
                                        mlp_b1 + i * MLP_DIM, nullptr, G,
                                        L_SEQ, MLP_DIM,
                                        ln2_g + i * C_DIM, ln2_b + i * C_DIM, 1, 2);
        // mlp2 + residual
        gemm_sk_k<<<dim3(2, 40), 256>>>(G, mlp_w2 + (size_t)i * MLP_DIM * C_DIM,
                                        mlp_b2 + i * C_DIM, X, X,
                                        L_SEQ, 128, MLP_DIM);
    }

    region_lnchan_k<<<N_IMG, 128>>>(support, query, X, rln_g, rln_b, FUSED, LNT);

    conv3x3_k<<<dim3(N_IMG, 4), 256, C_DIM * 144 * sizeof(float)>>>(LNT, conv1, T1, C_DIM, 1);
    conv3x3_k<<<dim3(N_IMG, 4), 256, T_CH * 144 * sizeof(float)>>>(T1, conv2, T2, T_CH, 1);
    conv3x3_k<<<dim3(N_IMG, 4), 256, T_CH * 144 * sizeof(float)>>>(T2, conv3, T1, T_CH, 1);
    conv3x3_k<<<dim3(N_IMG, 4), 256, T_CH * 144 * sizeof(float)>>>(T1, conv4, T2, T_CH, 0);

    rfm_out_k<<<N_IMG, 256>>>(T2, FUSED, (float*)d_out);
}

// round 6
// speedup vs baseline: 1.0188x; 1.0188x over previous
#include <cuda_runtime.h>
#include <cuda_bf16.h>
#include <cuda_fp16.h>
#include <math.h>

// ---------------------------------------------------------------------------
// Problem constants
// ---------------------------------------------------------------------------
#define L_SEQ   2516          // 16 + 25*100
#define C_DIM   128
#define HEADS_N 8
#define DH      16
#define MLP_DIM 512
#define N_IMG   100           // 25 support + 75 query
#define HW      100           // 10x10
#define T_CH    32
#define KSPAN   256           // keys per split (multiple of 64)
#define KSPLIT  10            // ceil(2516/256)
// score scale in log2 domain: dh^-0.5 * log2(e)
#define SCL     0.36067376022224085f

typedef unsigned long long ull;

// ---- packed fp32x2 helpers (Blackwell FFMA2) ------------------------------
__device__ __forceinline__ ull mul2(ull a, ull b) {
    ull r; asm("mul.rn.f32x2 %0,%1,%2;" : "=l"(r) : "l"(a), "l"(b)); return r;
}
__device__ __forceinline__ void fma2(ull &d, ull a, ull b) {
    asm("fma.rn.f32x2 %0,%1,%2,%0;" : "+l"(d) : "l"(a), "l"(b));
}
__device__ __forceinline__ ull add2(ull a, ull b) {
    ull r; asm("add.rn.f32x2 %0,%1,%2;" : "=l"(r) : "l"(a), "l"(b)); return r;
}
__device__ __forceinline__ ull pack2(float x, float y) {
    ull r; asm("mov.b64 %0,{%1,%2};" : "=l"(r) : "f"(x), "f"(y)); return r;
}
__device__ __forceinline__ float2 unpack2(ull a) {
    float x, y; asm("mov.b64 {%0,%1},%2;" : "=f"(x), "=f"(y) : "l"(a));
    return make_float2(x, y);
}
// packed half2 exp2: 2 exps per MUFU op
__device__ __forceinline__ float2 exp2_pair(float a, float b) {
    __half2 h = __floats2half2_rn(a, b);
    unsigned int hi = *(unsigned int*)&h;
    unsigned int r;
    asm("ex2.approx.f16x2 %0,%1;" : "=r"(r) : "r"(hi));
    __half2 e = *(__half2*)&r;
    return __half22float2(e);
}

// ---------------------------------------------------------------------------
// Scratch (device globals; no allocation allowed)
// ---------------------------------------------------------------------------
__device__ float g_X   [L_SEQ * C_DIM];
__device__ float g_QKV [L_SEQ * 3 * C_DIM];
__device__ float g_O   [L_SEQ * C_DIM];
__device__ float g_G   [L_SEQ * MLP_DIM];
__device__ float g_PART[KSPLIT * HEADS_N * L_SEQ * DH];
__device__ float g_ML  [KSPLIT * HEADS_N * L_SEQ * 2];
__device__ float g_FUSED[N_IMG * C_DIM * HW];
__device__ float g_LNT  [N_IMG * C_DIM * HW];
__device__ float g_T1   [N_IMG * T_CH * HW];
__device__ float g_T2   [N_IMG * T_CH * HW];

// ---------------------------------------------------------------------------
// build X = concat(task_descriptor, support permuted)
// ---------------------------------------------------------------------------
__global__ void build_x_k(const float* __restrict__ task,
                          const float* __restrict__ support,
                          float* __restrict__ X)
{
    int i = blockIdx.x * blockDim.x + threadIdx.x;
    if (i >= L_SEQ * C_DIM) return;
    int r = i >> 7;
    int c = i & 127;
    if (r < 16) {
        X[i] = task[r * C_DIM + c];
    } else {
        int rr = r - 16;
        int b = rr / HW, p = rr % HW;
        X[i] = support[b * C_DIM * HW + c * HW + p];
    }
}

// ---------------------------------------------------------------------------
// Fused (optional rowLN) + GEMM for K = 128.
// ---------------------------------------------------------------------------
__global__ void __launch_bounds__(256) ln_gemm_k(
    const float* __restrict__ A, const float* __restrict__ B,
    const float* __restrict__ bias, const float* __restrict__ res,
    float* __restrict__ C, int M, int N,
    const float* __restrict__ lg, const float* __restrict__ lb,
    int do_ln, int epi)
{
    __shared__ __align__(16) float Ast[128][68];   // [k][row]
    __shared__ __align__(16) float Bs[32][64];
    __shared__ float sg[128], sb[128];
    int bm = blockIdx.y * 64, bn = blockIdx.x * 64;
    int tid = threadIdx.x;
    if (do_ln && tid < 128) { sg[tid] = lg[tid]; sb[tid] = lb[tid]; }

    int row = tid >> 2, part = tid & 3;
    int grow = bm + row;
    float4 v[8];
#pragma unroll
    for (int i = 0; i < 8; i++) {
        int c = i * 16 + part * 4;
        v[i] = (grow < M) ? *(const float4*)&A[(size_t)grow * 128 + c]
                          : make_float4(0.f, 0.f, 0.f, 0.f);
    }
    __syncthreads();

    if (do_ln) {
        float s = 0.f;
#pragma unroll
        for (int i = 0; i < 8; i++) s += (v[i].x + v[i].y) + (v[i].z + v[i].w);
        s += __shfl_xor_sync(0xFFFFFFFFu, s, 1);
        s += __shfl_xor_sync(0xFFFFFFFFu, s, 2);
        float mean = s * (1.0f / 128.0f);
        float vv = 0.f;
#pragma unroll
        for (int i = 0; i < 8; i++) {
            float dx = v[i].x - mean, dy = v[i].y - mean;
            float dz = v[i].z - mean, dw = v[i].w - mean;
            vv += (dx * dx + dy * dy) + (dz * dz + dw * dw);
        }
        vv += __shfl_xor_sync(0xFFFFFFFFu, vv, 1);
        vv += __shfl_xor_sync(0xFFFFFFFFu, vv, 2);
        float rs = rsqrtf(vv * (1.0f / 128.0f) + 1e-5f);
#pragma unroll
        for (int i = 0; i < 8; i++) {
            int c = i * 16 + part * 4;
            v[i].x = (v[i].x - mean) * rs * sg[c + 0] + sb[c + 0];
            v[i].y = (v[i].y - mean) * rs * sg[c + 1] + sb[c + 1];
            v[i].z = (v[i].z - mean) * rs * sg[c + 2] + sb[c + 2];
            v[i].w = (v[i].w - mean) * rs * sg[c + 3] + sb[c + 3];
        }
    }
#pragma unroll
    for (int i = 0; i < 8; i++) {
        int c = i * 16 + part * 4;
        Ast[c + 0][row] = v[i].x;
        Ast[c + 1][row] = v[i].y;
        Ast[c + 2][row] = v[i].z;
        Ast[c + 3][row] = v[i].w;
    }
    __syncthreads();

    int tx = tid & 15, ty = tid >> 4;
    ull acc01[4] = {0, 0, 0, 0}, acc23[4] = {0, 0, 0, 0};

    for (int kk = 0; kk < 128; kk += 32) {
        if (kk) __syncthreads();
#pragma unroll
        for (int u = 0; u < 2; u++) {
            int idx = tid * 2 + u;
            int brow = idx >> 4, bcol = (idx & 15) * 4;
            *(float4*)&Bs[brow][bcol] =
                *(const float4*)&B[(size_t)(kk + brow) * N + bn + bcol];
        }
        __syncthreads();
#pragma unroll
        for (int k = 0; k < 32; k++) {
            float4 a4 = *(const float4*)&Ast[kk + k][ty * 4];
            ulonglong2 bp = *(const ulonglong2*)&Bs[k][tx * 4];
            ull aa;
            aa = pack2(a4.x, a4.x); fma2(acc01[0], aa, bp.x); fma2(acc23[0], aa, bp.y);
            aa = pack2(a4.y, a4.y); fma2(acc01[1], aa, bp.x); fma2(acc23[1], aa, bp.y);
            aa = pack2(a4.z, a4.z); fma2(acc01[2], aa, bp.x); fma2(acc23[2], aa, bp.y);
            aa = pack2(a4.w, a4.w); fma2(acc01[3], aa, bp.x); fma2(acc23[3], aa, bp.y);
        }
    }

#pragma unroll
    for (int i = 0; i < 4; i++) {
        int r = bm + ty * 4 + i;
        if (r >= M) continue;
        float2 c01 = unpack2(acc01[i]);
        float2 c23 = unpack2(acc23[i]);
        float vals[4] = {c01.x, c01.y, c23.x, c23.y};
#pragma unroll
        for (int j = 0; j < 4; j++) {
            int cidx = bn + tx * 4 + j;
            float o = vals[j] + bias[cidx];
            if (epi == 1) o += res[(size_t)r * N + cidx];
            else if (epi == 2) o = 0.5f * o * (1.0f + erff(o * 0.70710678118654752f));
            C[(size_t)r * N + cidx] = o;
        }
    }
}

// ---------------------------------------------------------------------------
// Streaming-K GEMM (for K=512), f32x2 inner. BM=BN=64, BK=16, epi=+bias+res.
// ---------------------------------------------------------------------------
__global__ void __launch_bounds__(256) gemm_sk_k(
    const float* __restrict__ A, const float* __restrict__ B,
    const float* __restrict__ bias, const float* __restrict__ res,
    float* __restrict__ C, int M, int N, int K)
{
    __shared__ __align__(16) float As[16][68];
    __shared__ __align__(16) float Bs[16][64];
    int bm = blockIdx.y * 64, bn = blockIdx.x * 64;
    int tid = threadIdx.x;
    int tx = tid & 15, ty = tid >> 4;
    ull acc01[4] = {0, 0, 0, 0}, acc23[4] = {0, 0, 0, 0};

    int ar = tid >> 2, ac = (tid & 3) * 4;
    int brow = tid >> 4, bcol = (tid & 15) * 4;

    for (int k0 = 0; k0 < K; k0 += 16) {
        float4 av = make_float4(0.f, 0.f, 0.f, 0.f);
        if (bm + ar < M)
            av = *(const float4*)&A[(size_t)(bm + ar) * K + k0 + ac];
        As[ac + 0][ar] = av.x;
        As[ac + 1][ar] = av.y;
        As[ac + 2][ar] = av.z;
        As[ac + 3][ar] = av.w;
        *(float4*)&Bs[brow][bcol] = *(const float4*)&B[(size_t)(k0 + brow) * N + bn + bcol];
        __syncthreads();
#pragma unroll
        for (int k = 0; k < 16; k++) {
            float4 a4 = *(const float4*)&As[k][ty * 4];
            ulonglong2 bp = *(const ulonglong2*)&Bs[k][tx * 4];
            ull aa;
            aa = pack2(a4.x, a4.x); fma2(acc01[0], aa, bp.x); fma2(acc23[0], aa, bp.y);
            aa = pack2(a4.y, a4.y); fma2(acc01[1], aa, bp.x); fma2(acc23[1], aa, bp.y);
            aa = pack2(a4.z, a4.z); fma2(acc01[2], aa, bp.x); fma2(acc23[2], aa, bp.y);
            aa = pack2(a4.w, a4.w); fma2(acc01[3], aa, bp.x); fma2(acc23[3], aa, bp.y);
        }
        __syncthreads();
    }
#pragma unroll
    for (int i = 0; i < 4; i++) {
        int r = bm + ty * 4 + i;
        if (r >= M) continue;
        float2 c01 = unpack2(acc01[i]);
        float2 c23 = unpack2(acc23[i]);
        float vals[4] = {c01.x, c01.y, c23.x, c23.y};
#pragma unroll
        for (int j = 0; j < 4; j++) {
            int cidx = bn + tx * 4 + j;
            float o = vals[j] + bias[cidx] + res[(size_t)r * N + cidx];
            C[(size_t)r * N + cidx] = o;
        }
    }
}

// ---------------------------------------------------------------------------
// Flash attention partials: 2 queries/thread x 2 keys/iter.
// Scores in log2 domain; packed f16x2 EX2 (2 exps per MUFU op).
// grid (10, heads=8, splits=10), block 128.
// ---------------------------------------------------------------------------
__global__ void __launch_bounds__(128)
attn_partial_k(const float* __restrict__ QKV,
               float* __restrict__ PART, float* __restrict__ ML)
{
    int h  = blockIdx.y;
    int sp = blockIdx.z;
    int tid = threadIdx.x;
    int q0 = blockIdx.x * 256 + tid;
    int q1 = q0 + 128;
    int k0 = sp * KSPAN;
    int k1 = min(L_SEQ, k0 + KSPAN);

    __shared__ __align__(16) float4 Ks[64][4];
    __shared__ __align__(16) float4 Vs[64][4];

    bool act0 = q0 < L_SEQ, act1 = q1 < L_SEQ;
    ull qa[8], qb[8];
#pragma unroll
    for (int u = 0; u < 4; u++) {
        ulonglong2 t = act0 ? *(const ulonglong2*)&QKV[(size_t)q0 * 384 + h * 16 + 4 * u]
                            : make_ulonglong2(0ull, 0ull);
        qa[2 * u] = t.x; qa[2 * u + 1] = t.y;
        ulonglong2 s = act1 ? *(const ulonglong2*)&QKV[(size_t)q1 * 384 + h * 16 + 4 * u]
                            : make_ulonglong2(0ull, 0ull);
        qb[2 * u] = s.x; qb[2 * u + 1] = s.y;
    }
    float m0 = -INFINITY, l0 = 0.f, m1 = -INFINITY, l1 = 0.f;
    ull A0[8] = {0,0,0,0,0,0,0,0}, A1[8] = {0,0,0,0,0,0,0,0};

    for (int kc = k0; kc < k1; kc += 64) {
        int n = min(64, k1 - kc);
        for (int idx = tid; idx < n * 4; idx += 128) {
            int row = idx >> 2, d4 = idx & 3;
            Ks[row][d4] = *(const float4*)&QKV[(size_t)(kc + row) * 384 + 128 + h * 16 + 4 * d4];
            Vs[row][d4] = *(const float4*)&QKV[(size_t)(kc + row) * 384 + 256 + h * 16 + 4 * d4];
        }
        __syncthreads();
        for (int j = 0; j + 2 <= n; j += 2) {
            ull ka[8], kb[8];
#pragma unroll
            for (int u = 0; u < 4; u++) {
                ulonglong2 t = *(const ulonglong2*)&Ks[j][u];
                ka[2 * u] = t.x; ka[2 * u + 1] = t.y;
                ulonglong2 s = *(const ulonglong2*)&Ks[j + 1][u];
                kb[2 * u] = s.x; kb[2 * u + 1] = s.y;
            }
            ull c0, c1;
            c0 = mul2(qa[0], ka[0]); c1 = mul2(qa[1], ka[1]);
            fma2(c0, qa[2], ka[2]);  fma2(c1, qa[3], ka[3]);
            fma2(c0, qa[4], ka[4]);  fma2(c1, qa[5], ka[5]);
            fma2(c0, qa[6], ka[6]);  fma2(c1, qa[7], ka[7]);
            float2 f00 = unpack2(add2(c0, c1));
            float s00 = (f00.x + f00.y) * SCL;

            c0 = mul2(qa[0], kb[0]); c1 = mul2(qa[1], kb[1]);
            fma2(c0, qa[2], kb[2]);  fma2(c1, qa[3], kb[3]);
            fma2(c0, qa[4], kb[4]);  fma2(c1, qa[5], kb[5]);
            fma2(c0, qa[6], kb[6]);  fma2(c1, qa[7], kb[7]);
            float2 f01 = unpack2(add2(c0, c1));
            float s01 = (f01.x + f01.y) * SCL;

            c0 = mul2(qb[0], ka[0]); c1 = mul2(qb[1], ka[1]);
            fma2(c0, qb[2], ka[2]);  fma2(c1, qb[3], ka[3]);
            fma2(c0, qb[4], ka[4]);  fma2(c1, qb[5], ka[5]);
            fma2(c0, qb[6], ka[6]);  fma2(c1, qb[7], ka[7]);
            float2 f10 = unpack2(add2(c0, c1));
            float s10 = (f10.x + f10.y) * SCL;

            c0 = mul2(qb[0], kb[0]); c1 = mul2(qb[1], kb[1]);
            fma2(c0, qb[2], kb[2]);  fma2(c1, qb[3], kb[3]);
            fma2(c0, qb[4], kb[4]);  fma2(c1, qb[5], kb[5]);
            fma2(c0, qb[6], kb[6]);  fma2(c1, qb[7], kb[7]);
            float2 f11 = unpack2(add2(c0, c1));
            float s11 = (f11.x + f11.y) * SCL;

            float mp0 = fmaxf(s00, s01);
            if (mp0 > m0) {
                float corr = exp2f(m0 - mp0);
                l0 *= corr;
                ull cc = pack2(corr, corr);
#pragma unroll
                for (int u = 0; u < 8; u++) A0[u] = mul2(A0[u], cc);
                m0 = mp0;
            }
            float2 pf0 = exp2_pair(s00 - m0, s01 - m0);
            float p00 = pf0.x, p01 = pf0.y;
            l0 += p00 + p01;

            float mp1 = fmaxf(s10, s11);
            if (mp1 > m1) {
                float corr = exp2f(m1 - mp1);
                l1 *= corr;
                ull cc = pack2(corr, corr);
#pragma unroll
                for (int u = 0; u < 8; u++) A1[u] = mul2(A1[u], cc);
                m1 = mp1;
            }
            float2 pf1 = exp2_pair(s10 - m1, s11 - m1);
            float p10 = pf1.x, p11 = pf1.y;
            l1 += p10 + p11;

            ull pp00 = pack2(p00, p00), pp01 = pack2(p01, p01);
            ull pp10 = pack2(p10, p10), pp11 = pack2(p11, p11);
#pragma unroll
            for (int u = 0; u < 4; u++) {
                ulonglong2 va = *(const ulonglong2*)&Vs[j][u];
                ulonglong2 vb = *(const ulonglong2*)&Vs[j + 1][u];
                fma2(A0[2 * u],     pp00, va.x); fma2(A0[2 * u],     pp01, vb.x);
                fma2(A0[2 * u + 1], pp00, va.y); fma2(A0[2 * u + 1], pp01, vb.y);
                fma2(A1[2 * u],     pp10, va.x); fma2(A1[2 * u],     pp11, vb.x);
                fma2(A1[2 * u + 1], pp10, va.y); fma2(A1[2 * u + 1], pp11, vb.y);
            }
        }
        __syncthreads();
    }
    if (act0) {
        size_t idx = ((size_t)(sp * HEADS_N + h) * L_SEQ + q0);
        ulonglong2* pb = (ulonglong2*)&PART[idx * 16];
#pragma unroll
        for (int u = 0; u < 4; u++) pb[u] = make_ulonglong2(A0[2 * u], A0[2 * u + 1]);
        ML[idx * 2 + 0] = m0;
        ML[idx * 2 + 1] = l0;
    }
    if (act1) {
        size_t idx = ((size_t)(sp * HEADS_N + h) * L_SEQ + q1);
        ulonglong2* pb = (ulonglong2*)&PART[idx * 16];
#pragma unroll
        for (int u = 0; u < 4; u++) pb[u] = make_ulonglong2(A1[2 * u], A1[2 * u + 1]);
        ML[idx * 2 + 0] = m1;
        ML[idx * 2 + 1] = l1;
    }
}

// ---------------------------------------------------------------------------
// Merge: one warp per (h,q), lane d in [0,16). grid 2516 blocks x 256.
// m values are in log2 domain -> exp2f weights.
// ---------------------------------------------------------------------------
__global__ void __launch_bounds__(256)
attn_merge_k(const float* __restrict__ PART, const float* __restrict__ ML,
             float* __restrict__ O)
{
    int gw = blockIdx.x * 8 + (threadIdx.x >> 5);   // global warp id = h*L + q
    int lane = threadIdx.x & 31;
    int h = gw / L_SEQ, q = gw % L_SEQ;
    float w[KSPLIT];
    float M = -INFINITY;
#pragma unroll
    for (int sp = 0; sp < KSPLIT; sp++) {
        size_t idx = ((size_t)(sp * HEADS_N + h) * L_SEQ + q);
        w[sp] = ML[idx * 2 + 0];
        M = fmaxf(M, w[sp]);
    }
    float wsum = 0.0f;
#pragma unroll
    for (int sp = 0; sp < KSPLIT; sp++) {
        size_t idx = ((size_t)(sp * HEADS_N + h) * L_SEQ + q);
        float e = exp2f(w[sp] - M);
        wsum += ML[idx * 2 + 1] * e;
        w[sp] = e;
    }
    float inv = 1.0f / wsum;
    if (lane < DH) {
        float o = 0.0f;
#pragma unroll
        for (int sp = 0; sp < KSPLIT; sp++) {
            size_t idx = ((size_t)(sp * HEADS_N + h) * L_SEQ + q);
            o += PART[idx * 16 + lane] * w[sp];
        }
        O[(size_t)q * C_DIM + h * DH + lane] = o * inv;
    }
}

// ---------------------------------------------------------------------------
// Fused region + map_fuse + channel LayerNorm. One block/image, 128 threads.
// ---------------------------------------------------------------------------
__global__ void region_lnchan_k(const float* __restrict__ support,
                                const float* __restrict__ query,
                                const float* __restrict__ X,
                                const float* __restrict__ rg,
                                const float* __restrict__ rb,
                                float* __restrict__ F,
                                float* __restrict__ LNT)
{
    int img = blockIdx.x;
    __shared__ float key[16 * C_DIM];
    for (int i = threadIdx.x; i < 16 * C_DIM; i += 128) key[i] = X[i];
    __syncthreads();
    const float* feat = (img < 25) ? support + (size_t)img * C_DIM * HW
                                   : query + (size_t)(img - 25) * C_DIM * HW;
    float* fb  = F   + (size_t)img * C_DIM * HW;
    float* lb_ = LNT + (size_t)img * C_DIM * HW;
    int p = threadIdx.x;
    if (p >= HW) return;

    float dot[16];
#pragma unroll
    for (int m = 0; m < 16; m++) dot[m] = 0.0f;
    float fsum = 0.0f;
    for (int c = 0; c < C_DIM; c++) {
        float f = feat[c * HW + p];
        fsum += f;
#pragma unroll
        for (int m = 0; m < 16; m++) dot[m] += key[m * C_DIM + c] * f;
    }
    float s = 0.0f;
#pragma unroll
    for (int m = 0; m < 16; m++)
        s += 1.0f / (1.0f + __expf(-dot[m] * (1.0f / 128.0f)));
    s = s * (1.0f / 16.0f) + 1.0f;

    float mean = s * fsum * (1.0f / 128.0f);
    float var = 0.0f;
    for (int c = 0; c < C_DIM; c++) {
        float d = feat[c * HW + p] * s - mean;
        var += d * d;
    }
    float rs = rsqrtf(var * (1.0f / 128.0f) + 1e-6f);
    for (int c = 0; c < C_DIM; c++) {
        float fu = feat[c * HW + p] * s;
        fb[c * HW + p] = fu;
        lb_[c * HW + p] = (fu - mean) * rs * rg[c] + rb[c];
    }
}

// ---------------------------------------------------------------------------
// 3x3 conv, pad 1, 10x10, Cout=32. grid (image, 4): 8 oc/block, 256 threads.
// Input AND weights staged in smem.
// ---------------------------------------------------------------------------
__global__ void conv3x3_k(const float* __restrict__ in, const float* __restrict__ w,
                          float* __restrict__ out, int Cin, int do_relu)
{
    extern __shared__ float smem_c[];
    float* s_in = smem_c;                 // Cin*144
    float* s_w  = smem_c + Cin * 144;     // 8*Cin*9
    int img = blockIdx.x;
    int tid = threadIdx.x;
    const float* inb = in + (size_t)img * Cin * HW;
    for (int idx = tid; idx < Cin * 144; idx += 256) {
        int c = idx / 144, pos = idx % 144;
        int y = pos / 12 - 1, x = pos % 12 - 1;
        float v = 0.0f;
        if (y >= 0 && y < 10 && x >= 0 && x < 10) v = inb[c * HW + y * 10 + x];
        s_in[idx] = v;
    }
    int nw = 8 * Cin * 9;
    const float* wsrc = w + (size_t)blockIdx.y * 8 * Cin * 9;
    for (int idx = tid; idx < nw; idx += 256) s_w[idx] = wsrc[idx];
    __syncthreads();

    int ocl = tid >> 5;                   // 0..7 local oc
    int oc = blockIdx.y * 8 + ocl;
    int lane = tid & 31;
    float acc[4];
    int base[4];
#pragma unroll
    for (int t = 0; t < 4; t++) {
        acc[t] = 0.0f;
        int p = lane + 32 * t;
        if (p > 99) p = 99;
        int y = p / 10, x = p % 10;
        base[t] = y * 12 + x;
    }
    const float* wb = s_w + ocl * Cin * 9;
    for (int c = 0; c < Cin; c++) {
        const float* sc = s_in + c * 144;
#pragma unroll
        for (int kk = 0; kk < 9; kk++) {
            float wv = wb[c * 9 + kk];
            int off = (kk / 3) * 12 + (kk % 3);
#pragma unroll
            for (int t = 0; t < 4; t++)
                acc[t] += sc[base[t] + off] * wv;
        }
    }
    float* ob = out + (size_t)img * T_CH * HW + oc * HW;
#pragma unroll
    for (int t = 0; t < 4; t++) {
        int p = lane + 32 * t;
        if (p < HW) {
            float v = acc[t];
            if (do_relu) v = fmaxf(v, 0.0f);
            ob[p] = v;
        }
    }
}

// ---------------------------------------------------------------------------
// Final: out[b][c][t] = (1/100) * sum_p sigmoid(T4[b][t][p]) * F[b][c][p]
// ---------------------------------------------------------------------------
__global__ void rfm_out_k(const float* __restrict__ T4, const float* __restrict__ F,
                          float* __restrict__ out)
{
    int img = blockIdx.x;
    __shared__ float sig[HW * T_CH];  // [p][t]
    int tid = threadIdx.x;
    for (int idx = tid; idx < T_CH * HW; idx += 256) {
        int t = idx / HW, p = idx % HW;
        float v = T4[(size_t)img * T_CH * HW + idx];
        sig[p * T_CH + t] = 1.0f / (1.0f + __expf(-v));
    }
    __syncthreads();
    float* ob = out + (size_t)img * 4096;
    const float* fb = F + (size_t)img * C_DIM * HW;
    for (int o = tid; o < C_DIM * T_CH; o += 256) {
        int c = o >> 5, t = o & 31;
        float s = 0.0f;
        for (int p = 0; p < HW; p++)
            s += fb[c * HW + p] * sig[p * T_CH + t];
        ob[c * T_CH + t] = s * (1.0f / 100.0f);
    }
}

// ---------------------------------------------------------------------------
// Host launcher
// ---------------------------------------------------------------------------
extern "C" void kernel_launch(void* const* d_in, const int* in_sizes, int n_in,
                              void* d_out, int out_size)
{
    const float* support = (const float*)d_in[0];
    const float* query   = (const float*)d_in[1];
    const float* task    = (const float*)d_in[2];
    const float* ln1_g   = (const float*)d_in[3];
    const float* ln1_b   = (const float*)d_in[4];
    const float* qkv_w   = (const float*)d_in[5];
    const float* qkv_b   = (const float*)d_in[6];
    const float* out_w   = (const float*)d_in[7];
    const float* out_b   = (const float*)d_in[8];
    const float* ln2_g   = (const float*)d_in[9];
    const float* ln2_b   = (const float*)d_in[10];
    const float* mlp_w1  = (const float*)d_in[11];
    const float* mlp_b1  = (const float*)d_in[12];
    const float* mlp_w2  = (const float*)d_in[13];
    const float* mlp_b2  = (const float*)d_in[14];
    const float* rln_g   = (const float*)d_in[15];
    const float* rln_b   = (const float*)d_in[16];
    const float* conv1   = (const float*)d_in[17];
    const float* conv2   = (const float*)d_in[18];
    const float* conv3   = (const float*)d_in[19];
    const float* conv4   = (const float*)d_in[20];

    float *X, *QKV, *O, *G, *PART, *ML, *FUSED, *LNT, *T1, *T2;
    cudaGetSymbolAddress((void**)&X, g_X);
    cudaGetSymbolAddress((void**)&QKV, g_QKV);
    cudaGetSymbolAddress((void**)&O, g_O);
    cudaGetSymbolAddress((void**)&G, g_G);
    cudaGetSymbolAddress((void**)&PART, g_PART);
    cudaGetSymbolAddress((void**)&ML, g_ML);
    cudaGetSymbolAddress((void**)&FUSED, g_FUSED);
    cudaGetSymbolAddress((void**)&LNT, g_LNT);
    cudaGetSymbolAddress((void**)&T1, g_T1);
    cudaGetSymbolAddress((void**)&T2, g_T2);

    const int conv1_smem = (C_DIM * 144 + 8 * C_DIM * 9) * sizeof(float);   // 110592
    const int convN_smem = (T_CH * 144 + 8 * T_CH * 9) * sizeof(float);     // 27648
    cudaFuncSetAttribute(conv3x3_k, cudaFuncAttributeMaxDynamicSharedMemorySize,
                         conv1_smem);

    build_x_k<<<(L_SEQ * C_DIM + 255) / 256, 256>>>(task, support, X);

    for (int i = 0; i < 2; i++) {
        ln_gemm_k<<<dim3(6, 40), 256>>>(X, qkv_w + (size_t)i * C_DIM * 384,
                                        qkv_b + i * 384, nullptr, QKV,
                                        L_SEQ, 384,
                                        ln1_g + i * C_DIM, ln1_b + i * C_DIM, 1, 0);
        attn_partial_k<<<dim3(10, HEADS_N, KSPLIT), 128>>>(QKV, PART, ML);
        attn_merge_k<<<(HEADS_N * L_SEQ) / 8, 256>>>(PART, ML, O);
        ln_gemm_k<<<dim3(2, 40), 256>>>(O, out_w + (size_t)i * C_DIM * C_DIM,
                                        out_b + i * C_DIM, X, X,
                                        L_SEQ, 128, nullptr, nullptr, 0, 1);
        ln_gemm_k<<<dim3(8, 40), 256>>>(X, mlp_w1 + (size_t)i * C_DIM * MLP_DIM,
                                        mlp_b1 + i * MLP_DIM, nullptr, G,
                                        L_SEQ, MLP_DIM,
                                        ln2_g + i * C_DIM, ln2_b + i * C_DIM, 1, 2);
        gemm_sk_k<<<dim3(2, 40), 256>>>(G, mlp_w2 + (size_t)i * MLP_DIM * C_DIM,
                                        mlp_b2 + i * C_DIM, X, X,
                                        L_SEQ, 128, MLP_DIM);
    }

    region_lnchan_k<<<N_IMG, 128>>>(support, query, X, rln_g, rln_b, FUSED, LNT);

    conv3x3_k<<<dim3(N_IMG, 4), 256, conv1_smem>>>(LNT, conv1, T1, C_DIM, 1);
    conv3x3_k<<<dim3(N_IMG, 4), 256, convN_smem>>>(T1, conv2, T2, T_CH, 1);
    conv3x3_k<<<dim3(N_IMG, 4), 256, convN_smem>>>(T2, conv3, T1, T_CH, 1);
    conv3x3_k<<<dim3(N_IMG, 4), 256, convN_smem>>>(T1, conv4, T2, T_CH, 0);

    rfm_out_k<<<N_IMG, 256>>>(T2, FUSED, (float*)d_out);
}

// round 7
// speedup vs baseline: 1.0451x; 1.0258x over previous
#include <cuda_runtime.h>
#include <cuda_bf16.h>
#include <cuda_fp16.h>
#include <math.h>

// ---------------------------------------------------------------------------
#define L_SEQ   2516
#define C_DIM   128
#define HEADS_N 8
#define DH      16
#define MLP_DIM 512
#define N_IMG   100
#define HW      100
#define T_CH    32
#define KSPLIT  7
#define KSPAN   384           // 7*384 = 2688 >= 2516
#define SCL     0.36067376022224085f   // dh^-0.5 * log2(e)

typedef unsigned long long ull;

__device__ __forceinline__ ull mul2(ull a, ull b) {
    ull r; asm("mul.rn.f32x2 %0,%1,%2;" : "=l"(r) : "l"(a), "l"(b)); return r;
}
__device__ __forceinline__ void fma2(ull &d, ull a, ull b) {
    asm("fma.rn.f32x2 %0,%1,%2,%0;" : "+l"(d) : "l"(a), "l"(b));
}
__device__ __forceinline__ ull add2(ull a, ull b) {
    ull r; asm("add.rn.f32x2 %0,%1,%2;" : "=l"(r) : "l"(a), "l"(b)); return r;
}
__device__ __forceinline__ ull pack2(float x, float y) {
    ull r; asm("mov.b64 %0,{%1,%2};" : "=l"(r) : "f"(x), "f"(y)); return r;
}
__device__ __forceinline__ float2 unpack2(ull a) {
    float x, y; asm("mov.b64 {%0,%1},%2;" : "=f"(x), "=f"(y) : "l"(a));
    return make_float2(x, y);
}
__device__ __forceinline__ float2 exp2_pair(float a, float b) {
    __half2 h = __floats2half2_rn(a, b);
    unsigned int hi = *(unsigned int*)&h;
    unsigned int r;
    asm("ex2.approx.f16x2 %0,%1;" : "=r"(r) : "r"(hi));
    __half2 e = *(__half2*)&r;
    return __half22float2(e);
}

// ---------------------------------------------------------------------------
__device__ float g_X   [L_SEQ * C_DIM];
__device__ float g_QKV [L_SEQ * 3 * C_DIM];
__device__ float g_O   [L_SEQ * C_DIM];
__device__ float g_G   [L_SEQ * MLP_DIM];
__device__ float g_PART[KSPLIT * HEADS_N * L_SEQ * DH];
__device__ float g_ML  [KSPLIT * HEADS_N * L_SEQ];
__device__ float g_KMAX[HEADS_N];
__device__ float g_FUSED[N_IMG * C_DIM * HW];
__device__ float g_LNT  [N_IMG * C_DIM * HW];
__device__ float g_T1   [N_IMG * T_CH * HW];
__device__ float g_T2   [N_IMG * T_CH * HW];

// ---------------------------------------------------------------------------
__global__ void build_x_k(const float* __restrict__ task,
                          const float* __restrict__ support,
                          float* __restrict__ X)
{
    int i = blockIdx.x * blockDim.x + threadIdx.x;
    if (i >= L_SEQ * C_DIM) return;
    int r = i >> 7;
    int c = i & 127;
    if (r < 16) {
        X[i] = task[r * C_DIM + c];
    } else {
        int rr = r - 16;
        int b = rr / HW, p = rr % HW;
        X[i] = support[b * C_DIM * HW + c * HW + p];
    }
}

// ---------------------------------------------------------------------------
// Fused (optional rowLN) + GEMM for K = 128.
// ---------------------------------------------------------------------------
__global__ void __launch_bounds__(256) ln_gemm_k(
    const float* __restrict__ A, const float* __restrict__ B,
    const float* __restrict__ bias, const float* __restrict__ res,
    float* __restrict__ C, int M, int N,
    const float* __restrict__ lg, const float* __restrict__ lb,
    int do_ln, int epi)
{
    __shared__ __align__(16) float Ast[128][68];
    __shared__ __align__(16) float Bs[32][64];
    __shared__ float sg[128], sb[128];
    int bm = blockIdx.y * 64, bn = blockIdx.x * 64;
    int tid = threadIdx.x;
    if (do_ln && tid < 128) { sg[tid] = lg[tid]; sb[tid] = lb[tid]; }

    int row = tid >> 2, part = tid & 3;
    int grow = bm + row;
    float4 v[8];
#pragma unroll
    for (int i = 0; i < 8; i++) {
        int c = i * 16 + part * 4;
        v[i] = (grow < M) ? *(const float4*)&A[(size_t)grow * 128 + c]
                          : make_float4(0.f, 0.f, 0.f, 0.f);
    }
    __syncthreads();

    if (do_ln) {
        float s = 0.f;
#pragma unroll
        for (int i = 0; i < 8; i++) s += (v[i].x + v[i].y) + (v[i].z + v[i].w);
        s += __shfl_xor_sync(0xFFFFFFFFu, s, 1);
        s += __shfl_xor_sync(0xFFFFFFFFu, s, 2);
        float mean = s * (1.0f / 128.0f);
        float vv = 0.f;
#pragma unroll
        for (int i = 0; i < 8; i++) {
            float dx = v[i].x - mean, dy = v[i].y - mean;
            float dz = v[i].z - mean, dw = v[i].w - mean;
            vv += (dx * dx + dy * dy) + (dz * dz + dw * dw);
        }
        vv += __shfl_xor_sync(0xFFFFFFFFu, vv, 1);
        vv += __shfl_xor_sync(0xFFFFFFFFu, vv, 2);
        float rs = rsqrtf(vv * (1.0f / 128.0f) + 1e-5f);
#pragma unroll
        for (int i = 0; i < 8; i++) {
            int c = i * 16 + part * 4;
            v[i].x = (v[i].x - mean) * rs * sg[c + 0] + sb[c + 0];
            v[i].y = (v[i].y - mean) * rs * sg[c + 1] + sb[c + 1];
            v[i].z = (v[i].z - mean) * rs * sg[c + 2] + sb[c + 2];
            v[i].w = (v[i].w - mean) * rs * sg[c + 3] + sb[c + 3];
        }
    }
#pragma unroll
    for (int i = 0; i < 8; i++) {
        int c = i * 16 + part * 4;
        Ast[c + 0][row] = v[i].x;
        Ast[c + 1][row] = v[i].y;
        Ast[c + 2][row] = v[i].z;
        Ast[c + 3][row] = v[i].w;
    }
    __syncthreads();

    int tx = tid & 15, ty = tid >> 4;
    ull acc01[4] = {0, 0, 0, 0}, acc23[4] = {0, 0, 0, 0};

    for (int kk = 0; kk < 128; kk += 32) {
        if (kk) __syncthreads();
#pragma unroll
        for (int u = 0; u < 2; u++) {
            int idx = tid * 2 + u;
            int brow = idx >> 4, bcol = (idx & 15) * 4;
            *(float4*)&Bs[brow][bcol] =
                *(const float4*)&B[(size_t)(kk + brow) * N + bn + bcol];
        }
        __syncthreads();
#pragma unroll
        for (int k = 0; k < 32; k++) {
            float4 a4 = *(const float4*)&Ast[kk + k][ty * 4];
            ulonglong2 bp = *(const ulonglong2*)&Bs[k][tx * 4];
            ull aa;
            aa = pack2(a4.x, a4.x); fma2(acc01[0], aa, bp.x); fma2(acc23[0], aa, bp.y);
            aa = pack2(a4.y, a4.y); fma2(acc01[1], aa, bp.x); fma2(acc23[1], aa, bp.y);
            aa = pack2(a4.z, a4.z); fma2(acc01[2], aa, bp.x); fma2(acc23[2], aa, bp.y);
            aa = pack2(a4.w, a4.w); fma2(acc01[3], aa, bp.x); fma2(acc23[3], aa, bp.y);
        }
    }

#pragma unroll
    for (int i = 0; i < 4; i++) {
        int r = bm + ty * 4 + i;
        if (r >= M) continue;
        float2 c01 = unpack2(acc01[i]);
        float2 c23 = unpack2(acc23[i]);
        float vals[4] = {c01.x, c01.y, c23.x, c23.y};
#pragma unroll
        for (int j = 0; j < 4; j++) {
            int cidx = bn + tx * 4 + j;
            float o = vals[j] + bias[cidx];
            if (epi == 1) o += res[(size_t)r * N + cidx];
            else if (epi == 2) o = 0.5f * o * (1.0f + erff(o * 0.70710678118654752f));
            C[(size_t)r * N + cidx] = o;
        }
    }
}

// ---------------------------------------------------------------------------
// Streaming-K GEMM (K=512), f32x2 inner, epi = +bias+res.
// ---------------------------------------------------------------------------
__global__ void __launch_bounds__(256) gemm_sk_k(
    const float* __restrict__ A, const float* __restrict__ B,
    const float* __restrict__ bias, const float* __restrict__ res,
    float* __restrict__ C, int M, int N, int K)
{
    __shared__ __align__(16) float As[16][68];
    __shared__ __align__(16) float Bs[16][64];
    int bm = blockIdx.y * 64, bn = blockIdx.x * 64;
    int tid = threadIdx.x;
    int tx = tid & 15, ty = tid >> 4;
    ull acc01[4] = {0, 0, 0, 0}, acc23[4] = {0, 0, 0, 0};

    int ar = tid >> 2, ac = (tid & 3) * 4;
    int brow = tid >> 4, bcol = (tid & 15) * 4;

    for (int k0 = 0; k0 < K; k0 += 16) {
        float4 av = make_float4(0.f, 0.f, 0.f, 0.f);
        if (bm + ar < M)
            av = *(const float4*)&A[(size_t)(bm + ar) * K + k0 + ac];
        As[ac + 0][ar] = av.x;
        As[ac + 1][ar] = av.y;
        As[ac + 2][ar] = av.z;
        As[ac + 3][ar] = av.w;
        *(float4*)&Bs[brow][bcol] = *(const float4*)&B[(size_t)(k0 + brow) * N + bn + bcol];
        __syncthreads();
#pragma unroll
        for (int k = 0; k < 16; k++) {
            float4 a4 = *(const float4*)&As[k][ty * 4];
            ulonglong2 bp = *(const ulonglong2*)&Bs[k][tx * 4];
            ull aa;
            aa = pack2(a4.x, a4.x); fma2(acc01[0], aa, bp.x); fma2(acc23[0], aa, bp.y);
            aa = pack2(a4.y, a4.y); fma2(acc01[1], aa, bp.x); fma2(acc23[1], aa, bp.y);
            aa = pack2(a4.z, a4.z); fma2(acc01[2], aa, bp.x); fma2(acc23[2], aa, bp.y);
            aa = pack2(a4.w, a4.w); fma2(acc01[3], aa, bp.x); fma2(acc23[3], aa, bp.y);
        }
        __syncthreads();
    }
#pragma unroll
    for (int i = 0; i < 4; i++) {
        int r = bm + ty * 4 + i;
        if (r >= M) continue;
        float2 c01 = unpack2(acc01[i]);
        float2 c23 = unpack2(acc23[i]);
        float vals[4] = {c01.x, c01.y, c23.x, c23.y};
#pragma unroll
        for (int j = 0; j < 4; j++) {
            int cidx = bn + tx * 4 + j;
            float o = vals[j] + bias[cidx] + res[(size_t)r * N + cidx];
            C[(size_t)r * N + cidx] = o;
        }
    }
}

// ---------------------------------------------------------------------------
// Per-head max key norm (Cauchy–Schwarz bound for exp args). 8 blocks x 256.
// ---------------------------------------------------------------------------
__global__ void knorm_k(const float* __restrict__ QKV, float* __restrict__ KMAX)
{
    int h = blockIdx.x;
    int tid = threadIdx.x;
    float mx = 0.0f;
    for (int k = tid; k < L_SEQ; k += 256) {
        const float4* kp = (const float4*)&QKV[(size_t)k * 384 + 128 + h * 16];
        float n2 = 0.0f;
#pragma unroll
        for (int u = 0; u < 4; u++) {
            float4 vv = kp[u];
            n2 += (vv.x * vv.x + vv.y * vv.y) + (vv.z * vv.z + vv.w * vv.w);
        }
        mx = fmaxf(mx, n2);
    }
#pragma unroll
    for (int o = 16; o > 0; o >>= 1) mx = fmaxf(mx, __shfl_xor_sync(0xFFFFFFFFu, mx, o));
    __shared__ float ws[8];
    if ((tid & 31) == 0) ws[tid >> 5] = mx;
    __syncthreads();
    if (tid == 0) {
        float m = ws[0];
#pragma unroll
        for (int i = 1; i < 8; i++) m = fmaxf(m, ws[i]);
        KMAX[h] = sqrtf(m);
    }
}

// ---------------------------------------------------------------------------
// Flash attention partials: 4 queries/thread x 2 keys/iter.
// Global per-query bound m_q (no online max, no rescale, no branches).
// grid (5, 8, 7), block 128.
// ---------------------------------------------------------------------------
__global__ void __launch_bounds__(128)
attn_partial_k(const float* __restrict__ QKV, const float* __restrict__ KMAX,
               float* __restrict__ PART, float* __restrict__ ML)
{
    int h  = blockIdx.y;
    int sp = blockIdx.z;
    int tid = threadIdx.x;
    int qbase = blockIdx.x * 512 + tid;
    int k0 = sp * KSPAN;
    int k1 = min(L_SEQ, k0 + KSPAN);

    __shared__ __align__(16) float4 Ks[64][4];
    __shared__ __align__(16) float4 Vs[64][4];

    float kmax = KMAX[h];

    ull Q[4][8];
    float m[4], l[4];
    ull A[4][8];
    bool act[4];
#pragma unroll
    for (int i = 0; i < 4; i++) {
        int qi = qbase + 128 * i;
        act[i] = qi < L_SEQ;
        float qn2 = 0.0f;
#pragma unroll
        for (int u = 0; u < 4; u++) {
            ulonglong2 t = act[i]
                ? *(const ulonglong2*)&QKV[(size_t)qi * 384 + h * 16 + 4 * u]
                : make_ulonglong2(0ull, 0ull);
            Q[i][2 * u] = t.x; Q[i][2 * u + 1] = t.y;
            float2 f0 = unpack2(t.x), f1 = unpack2(t.y);
            qn2 += (f0.x * f0.x + f0.y * f0.y) + (f1.x * f1.x + f1.y * f1.y);
        }
        m[i] = sqrtf(qn2) * kmax * SCL;   // >= every s*SCL for this query
        l[i] = 0.0f;
#pragma unroll
        for (int u = 0; u < 8; u++) A[i][u] = 0ull;
    }

    for (int kc = k0; kc < k1; kc += 64) {
        int n = min(64, k1 - kc);
        for (int idx = tid; idx < n * 4; idx += 128) {
            int row = idx >> 2, d4 = idx & 3;
            Ks[row][d4] = *(const float4*)&QKV[(size_t)(kc + row) * 384 + 128 + h * 16 + 4 * d4];
            Vs[row][d4] = *(const float4*)&QKV[(size_t)(kc + row) * 384 + 256 + h * 16 + 4 * d4];
        }
        __syncthreads();
        for (int j = 0; j + 2 <= n; j += 2) {
            ull ka[8], kb[8], va[8], vb[8];
#pragma unroll
            for (int u = 0; u < 4; u++) {
                ulonglong2 t = *(const ulonglong2*)&Ks[j][u];
                ka[2 * u] = t.x; ka[2 * u + 1] = t.y;
                ulonglong2 s = *(const ulonglong2*)&Ks[j + 1][u];
                kb[2 * u] = s.x; kb[2 * u + 1] = s.y;
                ulonglong2 tv = *(const ulonglong2*)&Vs[j][u];
                va[2 * u] = tv.x; va[2 * u + 1] = tv.y;
                ulonglong2 sv = *(const ulonglong2*)&Vs[j + 1][u];
                vb[2 * u] = sv.x; vb[2 * u + 1] = sv.y;
            }
#pragma unroll
            for (int i = 0; i < 4; i++) {
                ull c0, c1;
                c0 = mul2(Q[i][0], ka[0]); c1 = mul2(Q[i][1], ka[1]);
                fma2(c0, Q[i][2], ka[2]); fma2(c1, Q[i][3], ka[3]);
                fma2(c0, Q[i][4], ka[4]); fma2(c1, Q[i][5], ka[5]);
                fma2(c0, Q[i][6], ka[6]); fma2(c1, Q[i][7], ka[7]);
                float2 fa = unpack2(add2(c0, c1));
                float sa = fa.x + fa.y;

                c0 = mul2(Q[i][0], kb[0]); c1 = mul2(Q[i][1], kb[1]);
                fma2(c0, Q[i][2], kb[2]); fma2(c1, Q[i][3], kb[3]);
                fma2(c0, Q[i][4], kb[4]); fma2(c1, Q[i][5], kb[5]);
                fma2(c0, Q[i][6], kb[6]); fma2(c1, Q[i][7], kb[7]);
                float2 fb = unpack2(add2(c0, c1));
                float sb = fb.x + fb.y;

                float2 p = exp2_pair(fmaf(sa, SCL, -m[i]), fmaf(sb, SCL, -m[i]));
                l[i] += p.x + p.y;
                ull ppa = pack2(p.x, p.x);
                ull ppb = pack2(p.y, p.y);
#pragma unroll
                for (int u = 0; u < 8; u++) {
                    fma2(A[i][u], ppa, va[u]);
                    fma2(A[i][u], ppb, vb[u]);
                }
            }
        }
        __syncthreads();
    }
#pragma unroll
    for (int i = 0; i < 4; i++) {
        if (!act[i]) continue;
        int qi = qbase + 128 * i;
        size_t b = ((size_t)(sp * HEADS_N + h) * L_SEQ + qi);
        ulonglong2* pb = (ulonglong2*)&PART[b * 16];
#pragma unroll
        for (int u = 0; u < 4; u++)
            pb[u] = make_ulonglong2(A[i][2 * u], A[i][2 * u + 1]);
        ML[b] = l[i];
    }
}

// ---------------------------------------------------------------------------
// Merge: global m per (q,h) -> partials are directly summable.
// thread per (q,h,d). 1258 blocks x 256.
// ---------------------------------------------------------------------------
__global__ void __launch_bounds__(256)
attn_merge_k(const float* __restrict__ PART, const float* __restrict__ ML,
             float* __restrict__ O)
{
    int idx = blockIdx.x * 256 + threadIdx.x;
    if (idx >= L_SEQ * C_DIM) return;
    int d = idx & 15;
    int h = (idx >> 4) & 7;
    int q = idx >> 7;
    float num = 0.0f, den = 0.0f;
#pragma unroll
    for (int sp = 0; sp < KSPLIT; sp++) {
        size_t b = ((size_t)(sp * HEADS_N + h) * L_SEQ + q);
        num += PART[b * 16 + d];
        den += ML[b];
    }
    O[(size_t)q * C_DIM + h * DH + d] = num / den;
}

// ---------------------------------------------------------------------------
// Fused region + map_fuse + channel LayerNorm.
// ---------------------------------------------------------------------------
__global__ void region_lnchan_k(const float* __restrict__ support,
                                const float* __restrict__ query,
                                const float* __restrict__ X,
                                const float* __restrict__ rg,
                                const float* __restrict__ rb,
                                float* __restrict__ F,
                                float* __restrict__ LNT)
{
    int img = blockIdx.x;
    __shared__ float key[16 * C_DIM];
    for (int i = threadIdx.x; i < 16 * C_DIM; i += 128) key[i] = X[i];
    __syncthreads();
    const float* feat = (img < 25) ? support + (size_t)img * C_DIM * HW
                                   : query + (size_t)(img - 25) * C_DIM * HW;
    float* fb  = F   + (size_t)img * C_DIM * HW;
    float* lb_ = LNT + (size_t)img * C_DIM * HW;
    int p = threadIdx.x;
    if (p >= HW) return;

    float dot[16];
#pragma unroll
    for (int m = 0; m < 16; m++) dot[m] = 0.0f;
    float fsum = 0.0f;
    for (int c = 0; c < C_DIM; c++) {
        float f = feat[c * HW + p];
        fsum += f;
#pragma unroll
        for (int m = 0; m < 16; m++) dot[m] += key[m * C_DIM + c] * f;
    }
    float s = 0.0f;
#pragma unroll
    for (int m = 0; m < 16; m++)
        s += 1.0f / (1.0f + __expf(-dot[m] * (1.0f / 128.0f)));
    s = s * (1.0f / 16.0f) + 1.0f;

    float mean = s * fsum * (1.0f / 128.0f);
    float var = 0.0f;
    for (int c = 0; c < C_DIM; c++) {
        float d = feat[c * HW + p] * s - mean;
        var += d * d;
    }
    float rs = rsqrtf(var * (1.0f / 128.0f) + 1e-6f);
    for (int c = 0; c < C_DIM; c++) {
        float fu = feat[c * HW + p] * s;
        fb[c * HW + p] = fu;
        lb_[c * HW + p] = (fu - mean) * rs * rg[c] + rb[c];
    }
}

// ---------------------------------------------------------------------------
// 3x3 conv, pad 1, 10x10, Cout=32. grid (image, 4): 8 oc/block, 256 threads.
// ---------------------------------------------------------------------------
__global__ void conv3x3_k(const float* __restrict__ in, const float* __restrict__ w,
                          float* __restrict__ out, int Cin, int do_relu)
{
    extern __shared__ float smem_c[];
    float* s_in = smem_c;
    float* s_w  = smem_c + Cin * 144;
    int img = blockIdx.x;
    int tid = threadIdx.x;
    const float* inb = in + (size_t)img * Cin * HW;
    for (int idx = tid; idx < Cin * 144; idx += 256) {
        int c = idx / 144, pos = idx % 144;
        int y = pos / 12 - 1, x = pos % 12 - 1;
        float v = 0.0f;
        if (y >= 0 && y < 10 && x >= 0 && x < 10) v = inb[c * HW + y * 10 + x];
        s_in[idx] = v;
    }
    int nw = 8 * Cin * 9;
    const float* wsrc = w + (size_t)blockIdx.y * 8 * Cin * 9;
    for (int idx = tid; idx < nw; idx += 256) s_w[idx] = wsrc[idx];
    __syncthreads();

    int ocl = tid >> 5;
    int oc = blockIdx.y * 8 + ocl;
    int lane = tid & 31;
    float acc[4];
    int base[4];
#pragma unroll
    for (int t = 0; t < 4; t++) {
        acc[t] = 0.0f;
        int p = lane + 32 * t;
        if (p > 99) p = 99;
        int y = p / 10, x = p % 10;
        base[t] = y * 12 + x;
    }
    const float* wb = s_w + ocl * Cin * 9;
    for (int c = 0; c < Cin; c++) {
        const float* sc = s_in + c * 144;
#pragma unroll
        for (int kk = 0; kk < 9; kk++) {
            float wv = wb[c * 9 + kk];
            int off = (kk / 3) * 12 + (kk % 3);
#pragma unroll
            for (int t = 0; t < 4; t++)
                acc[t] += sc[base[t] + off] * wv;
        }
    }
    float* ob = out + (size_t)img * T_CH * HW + oc * HW;
#pragma unroll
    for (int t = 0; t < 4; t++) {
        int p = lane + 32 * t;
        if (p < HW) {
            float v = acc[t];
            if (do_relu) v = fmaxf(v, 0.0f);
            ob[p] = v;
        }
    }
}

// ---------------------------------------------------------------------------
// Final weighted pooling.
// ---------------------------------------------------------------------------
__global__ void rfm_out_k(const float* __restrict__ T4, const float* __restrict__ F,
                          float* __restrict__ out)
{
    int img = blockIdx.x;
    __shared__ float sig[HW * T_CH];
    int tid = threadIdx.x;
    for (int idx = tid; idx < T_CH * HW; idx += 256) {
        int t = idx / HW, p = idx % HW;
        float v = T4[(size_t)img * T_CH * HW + idx];
        sig[p * T_CH + t] = 1.0f / (1.0f + __expf(-v));
    }
    __syncthreads();
    float* ob = out + (size_t)img * 4096;
    const float* fb = F + (size_t)img * C_DIM * HW;
    for (int o = tid; o < C_DIM * T_CH; o += 256) {
        int c = o >> 5, t = o & 31;
        float s0 = 0.0f, s1 = 0.0f;
        for (int p = 0; p < HW; p += 2) {
            s0 += fb[c * HW + p]     * sig[p * T_CH + t];
            s1 += fb[c * HW + p + 1] * sig[(p + 1) * T_CH + t];
        }
        ob[c * T_CH + t] = (s0 + s1) * (1.0f / 100.0f);
    }
}

// ---------------------------------------------------------------------------
extern "C" void kernel_launch(void* const* d_in, const int* in_sizes, int n_in,
                              void* d_out, int out_size)
{
    const float* support = (const float*)d_in[0];
    const float* query   = (const float*)d_in[1];
    const float* task    = (const float*)d_in[2];
    const float* ln1_g   = (const float*)d_in[3];
    const float* ln1_b   = (const float*)d_in[4];
    const float* qkv_w   = (const float*)d_in[5];
    const float* qkv_b   = (const float*)d_in[6];
    const float* out_w   = (const float*)d_in[7];
    const float* out_b   = (const float*)d_in[8];
    const float* ln2_g   = (const float*)d_in[9];
    const float* ln2_b   = (const float*)d_in[10];
    const float* mlp_w1  = (const float*)d_in[11];
    const float* mlp_b1  = (const float*)d_in[12];
    const float* mlp_w2  = (const float*)d_in[13];
    const float* mlp_b2  = (const float*)d_in[14];
    const float* rln_g   = (const float*)d_in[15];
    const float* rln_b   = (const float*)d_in[16];
    const float* conv1   = (const float*)d_in[17];
    const float* conv2   = (const float*)d_in[18];
    const float* conv3   = (const float*)d_in[19];
    const float* conv4   = (const float*)d_in[20];

    float *X, *QKV, *O, *G, *PART, *ML, *KMAX, *FUSED, *LNT, *T1, *T2;
    cudaGetSymbolAddress((void**)&X, g_X);
    cudaGetSymbolAddress((void**)&QKV, g_QKV);
    cudaGetSymbolAddress((void**)&O, g_O);
    cudaGetSymbolAddress((void**)&G, g_G);
    cudaGetSymbolAddress((void**)&PART, g_PART);
    cudaGetSymbolAddress((void**)&ML, g_ML);
    cudaGetSymbolAddress((void**)&KMAX, g_KMAX);
    cudaGetSymbolAddress((void**)&FUSED, g_FUSED);
    cudaGetSymbolAddress((void**)&LNT, g_LNT);
    cudaGetSymbolAddress((void**)&T1, g_T1);
    cudaGetSymbolAddress((void**)&T2, g_T2);

    const int conv1_smem = (C_DIM * 144 + 8 * C_DIM * 9) * sizeof(float);
    const int convN_smem = (T_CH * 144 + 8 * T_CH * 9) * sizeof(float);
    cudaFuncSetAttribute(conv3x3_k, cudaFuncAttributeMaxDynamicSharedMemorySize,
                         conv1_smem);

    build_x_k<<<(L_SEQ * C_DIM + 255) / 256, 256>>>(task, support, X);

    for (int i = 0; i < 2; i++) {
        ln_gemm_k<<<dim3(6, 40), 256>>>(X, qkv_w + (size_t)i * C_DIM * 384,
                                        qkv_b + i * 384, nullptr, QKV,
                                        L_SEQ, 384,
                                        ln1_g + i * C_DIM, ln1_b + i * C_DIM, 1, 0);
        knorm_k<<<HEADS_N, 256>>>(QKV, KMAX);
        attn_partial_k<<<dim3(5, HEADS_N, KSPLIT), 128>>>(QKV, KMAX, PART, ML);
        attn_merge_k<<<(L_SEQ * C_DIM + 255) / 256, 256>>>(PART, ML, O);
        ln_gemm_k<<<dim3(2, 40), 256>>>(O, out_w + (size_t)i * C_DIM * C_DIM,
                                        out_b + i * C_DIM, X, X,
                                        L_SEQ, 128, nullptr, nullptr, 0, 1);
        ln_gemm_k<<<dim3(8, 40), 256>>>(X, mlp_w1 + (size_t)i * C_DIM * MLP_DIM,
                                        mlp_b1 + i * MLP_DIM, nullptr, G,
                                        L_SEQ, MLP_DIM,
                                        ln2_g + i * C_DIM, ln2_b + i * C_DIM, 1, 2);
        gemm_sk_k<<<dim3(2, 40), 256>>>(G, mlp_w2 + (size_t)i * MLP_DIM * C_DIM,
                                        mlp_b2 + i * C_DIM, X, X,
                                        L_SEQ, 128, MLP_DIM);
    }

    region_lnchan_k<<<N_IMG, 128>>>(support, query, X, rln_g, rln_b, FUSED, LNT);

    conv3x3_k<<<dim3(N_IMG, 4), 256, conv1_smem>>>(LNT, conv1, T1, C_DIM, 1);
    conv3x3_k<<<dim3(N_IMG, 4), 256, convN_smem>>>(T1, conv2, T2, T_CH, 1);
    conv3x3_k<<<dim3(N_IMG, 4), 256, convN_smem>>>(T2, conv3, T1, T_CH, 1);
    conv3x3_k<<<dim3(N_IMG, 4), 256, convN_smem>>>(T1, conv4, T2, T_CH, 0);

    rfm_out_k<<<N_IMG, 256>>>(T2, FUSED, (float*)d_out);
}